// round 11
// baseline (speedup 1.0000x reference)
#include <cuda_runtime.h>

#define N_CLASS  100
#define N_CENTER 4
#define HIDDEN   128
#define BATCH    2048
#define CHUNK    8

// Fully fused: one CTA per (class, center). Each CTA
//  1) compacts its class's sample list (deterministic warp-scan order),
//  2) accumulates S_c = sum x x^T in registers (acc[8][8], interleaved 16x16
//     tiling, conflict-free scalar LDS) and s_c = sum x in smem,
//  3) applies the epilogue for its center j directly from registers:
//     out = class_cov + S - mu_r*s_cc + (n*mu_r - s_r)*mu_cc.
// S_c never touches global memory.
__global__ void __launch_bounds__(256, 2) cov_fused_kernel(
    const float* __restrict__ x,          // [BATCH, HIDDEN]
    const int*   __restrict__ y,          // [BATCH]
    const float* __restrict__ class_mu,   // only class_mu[0] used: [N_CENTER, HIDDEN]
    const float* __restrict__ class_cov,  // [N_CLASS, N_CENTER, HIDDEN, HIDDEN]
    float* __restrict__ out)
{
    const int c = blockIdx.x;   // class
    const int j = blockIdx.y;   // center

    __shared__ float s_d[2][CHUNK][HIDDEN];
    __shared__ int   s_list[BATCH];
    __shared__ int   s_wsum[8];
    __shared__ float s_mu[HIDDEN];
    __shared__ float s_s[HIDDEN];

    const int tid  = threadIdx.x;
    const int lane = tid & 31;
    const int w    = tid >> 5;
    const int tx   = tid & 15;
    const int ty   = tid >> 4;

    if (tid < HIDDEN) s_mu[tid] = class_mu[j * HIDDEN + tid];

    // ---- Phase 1: deterministic in-CTA compaction ----
    int loc[8];
    int cnt = 0;
    {
        const int4* y4 = (const int4*)y;
        int4 a = y4[tid * 2];
        int4 b = y4[tid * 2 + 1];
        const int base = tid * 8;
        if (a.x == c) loc[cnt++] = base + 0;
        if (a.y == c) loc[cnt++] = base + 1;
        if (a.z == c) loc[cnt++] = base + 2;
        if (a.w == c) loc[cnt++] = base + 3;
        if (b.x == c) loc[cnt++] = base + 4;
        if (b.y == c) loc[cnt++] = base + 5;
        if (b.z == c) loc[cnt++] = base + 6;
        if (b.w == c) loc[cnt++] = base + 7;
    }
    int inc = cnt;
#pragma unroll
    for (int d = 1; d < 32; d <<= 1) {
        int v = __shfl_up_sync(0xffffffffu, inc, d);
        if (lane >= d) inc += v;
    }
    if (lane == 31) s_wsum[w] = inc;
    __syncthreads();
    int woff = 0, n = 0;
#pragma unroll
    for (int k = 0; k < 8; k++) {
        int s = s_wsum[k];
        if (k < w) woff += s;
        n += s;
    }
    const int off = woff + inc - cnt;
#pragma unroll
    for (int i = 0; i < 8; i++)
        if (i < cnt) s_list[off + i] = loc[i];
    __syncthreads();

    // ---- Phase 2: S_c in registers, s_c in smem ----
    float acc[8][8];
#pragma unroll
    for (int ri = 0; ri < 8; ri++)
#pragma unroll
        for (int ci = 0; ci < 8; ci++) acc[ri][ci] = 0.0f;
    float xsum = 0.0f;   // threads < 128 accumulate s_c[tid]

    const float4* x4 = (const float4*)x;
    const int nchunks = (n + CHUNK - 1) / CHUNK;
    const int gs = tid >> 5;   // sample row within chunk
    const int gq = tid & 31;   // float4 within row

    if (nchunks > 0) {
        float4 v = make_float4(0.f, 0.f, 0.f, 0.f);
        if (gs < n) v = x4[s_list[gs] * 32 + gq];
        ((float4*)s_d[0][gs])[gq] = v;
    }

    for (int k = 0; k < nchunks; k++) {
        __syncthreads();
        if (k + 1 < nchunks) {
            const int s0 = (k + 1) * CHUNK;
            float4 v = make_float4(0.f, 0.f, 0.f, 0.f);
            if (s0 + gs < n) v = x4[s_list[s0 + gs] * 32 + gq];
            ((float4*)s_d[(k + 1) & 1][gs])[gq] = v;
        }
        const float (*buf)[HIDDEN] = s_d[k & 1];
#pragma unroll
        for (int s = 0; s < CHUNK; s++) {
            float dr[8], dc[8];
#pragma unroll
            for (int ri = 0; ri < 8; ri++) dr[ri] = buf[s][ty + 16 * ri];
#pragma unroll
            for (int ci = 0; ci < 8; ci++) dc[ci] = buf[s][tx + 16 * ci];
#pragma unroll
            for (int ri = 0; ri < 8; ri++)
#pragma unroll
                for (int ci = 0; ci < 8; ci++)
                    acc[ri][ci] += dr[ri] * dc[ci];
            if (tid < HIDDEN) xsum += buf[s][tid];
        }
    }
    if (tid < HIDDEN) s_s[tid] = xsum;
    __syncthreads();

    // ---- Phase 3: epilogue straight from registers ----
    const float nf = (float)n;
    float mr[8], tr[8], mc[8], sc[8];
#pragma unroll
    for (int ri = 0; ri < 8; ri++) {
        const int r = ty + 16 * ri;
        mr[ri] = s_mu[r];
        tr[ri] = fmaf(nf, mr[ri], -s_s[r]);   // n*mu_r - s_r
    }
#pragma unroll
    for (int ci = 0; ci < 8; ci++) {
        const int cc = tx + 16 * ci;
        mc[ci] = s_mu[cc];
        sc[ci] = s_s[cc];
    }

    const size_t base = ((size_t)(c * N_CENTER + j)) * HIDDEN * HIDDEN;
#pragma unroll
    for (int ri = 0; ri < 8; ri++) {
        const int r = ty + 16 * ri;
        const float* cvrow = class_cov + base + (size_t)r * HIDDEN;
        float*       orow  = out       + base + (size_t)r * HIDDEN;
        float cv[8];
#pragma unroll
        for (int ci = 0; ci < 8; ci++) cv[ci] = cvrow[tx + 16 * ci];  // batched LDG
#pragma unroll
        for (int ci = 0; ci < 8; ci++) {
            float o = acc[ri][ci] + cv[ci];
            o = fmaf(-mr[ri], sc[ci], o);
            o = fmaf(tr[ri], mc[ci], o);
            orow[tx + 16 * ci] = o;
        }
    }
}

extern "C" void kernel_launch(void* const* d_in, const int* in_sizes, int n_in,
                              void* d_out, int out_size) {
    const float* x         = (const float*)d_in[0];
    const int*   y         = (const int*)d_in[1];
    const float* class_mu  = (const float*)d_in[2];
    const float* class_cov = (const float*)d_in[3];
    float*       out       = (float*)d_out;

    dim3 grid(N_CLASS, N_CENTER);
    cov_fused_kernel<<<grid, 256>>>(x, y, class_mu, class_cov, out);
}

// round 12
// speedup vs baseline: 1.2297x; 1.2297x over previous
#include <cuda_runtime.h>

#define N_CLASS  100
#define N_CENTER 4
#define HIDDEN   128
#define BATCH    2048
#define CHUNK    8

// Scratch (device globals; no runtime allocation allowed).
__device__ float g_S[N_CLASS * HIDDEN * HIDDEN];  // per-class sum of x x^T
__device__ float g_sum[N_CLASS * HIDDEN];         // per-class sum of x
__device__ int   g_n[N_CLASS];                    // per-class count

// ---------------- Stage A: per-class raw statistics ----------------
// grid = N_CLASS (one CTA per class, single wave on 148 SMs).
__global__ void __launch_bounds__(256, 2) stageA_kernel(
    const float* __restrict__ x, const int* __restrict__ y)
{
    const int c = blockIdx.x;

    __shared__ float s_d[2][CHUNK][HIDDEN];
    __shared__ int   s_list[BATCH];
    __shared__ int   s_wsum[8];

    const int tid  = threadIdx.x;
    const int lane = tid & 31;
    const int w    = tid >> 5;
    const int tx   = tid & 15;
    const int ty   = tid >> 4;

    // ---- deterministic in-CTA compaction of sample indices ----
    int loc[8];
    int cnt = 0;
    {
        const int4* y4 = (const int4*)y;
        int4 a = y4[tid * 2];
        int4 b = y4[tid * 2 + 1];
        const int base = tid * 8;
        if (a.x == c) loc[cnt++] = base + 0;
        if (a.y == c) loc[cnt++] = base + 1;
        if (a.z == c) loc[cnt++] = base + 2;
        if (a.w == c) loc[cnt++] = base + 3;
        if (b.x == c) loc[cnt++] = base + 4;
        if (b.y == c) loc[cnt++] = base + 5;
        if (b.z == c) loc[cnt++] = base + 6;
        if (b.w == c) loc[cnt++] = base + 7;
    }
    int inc = cnt;
#pragma unroll
    for (int d = 1; d < 32; d <<= 1) {
        int v = __shfl_up_sync(0xffffffffu, inc, d);
        if (lane >= d) inc += v;
    }
    if (lane == 31) s_wsum[w] = inc;
    __syncthreads();
    int woff = 0, n = 0;
#pragma unroll
    for (int k = 0; k < 8; k++) {
        int s = s_wsum[k];
        if (k < w) woff += s;
        n += s;
    }
    const int off = woff + inc - cnt;
#pragma unroll
    for (int i = 0; i < 8; i++)
        if (i < cnt) s_list[off + i] = loc[i];
    __syncthreads();

    // ---- rank-n accumulation of S = sum x x^T (raw x, zero-padded) ----
    float acc[8][8];
#pragma unroll
    for (int ri = 0; ri < 8; ri++)
#pragma unroll
        for (int ci = 0; ci < 8; ci++) acc[ri][ci] = 0.0f;
    float xsum = 0.0f;   // threads < 128 accumulate s_c[tid]

    const float4* x4 = (const float4*)x;
    const int nchunks = (n + CHUNK - 1) / CHUNK;
    const int gs = tid >> 5;   // sample row within chunk
    const int gq = tid & 31;   // float4 within row

    if (nchunks > 0) {
        float4 v = make_float4(0.f, 0.f, 0.f, 0.f);
        if (gs < n) v = x4[s_list[gs] * 32 + gq];
        ((float4*)s_d[0][gs])[gq] = v;
    }

    for (int k = 0; k < nchunks; k++) {
        __syncthreads();
        if (k + 1 < nchunks) {
            const int s0 = (k + 1) * CHUNK;
            float4 v = make_float4(0.f, 0.f, 0.f, 0.f);
            if (s0 + gs < n) v = x4[s_list[s0 + gs] * 32 + gq];
            ((float4*)s_d[(k + 1) & 1][gs])[gq] = v;
        }
        const float (*buf)[HIDDEN] = s_d[k & 1];
#pragma unroll
        for (int s = 0; s < CHUNK; s++) {
            float dr[8], dc[8];
#pragma unroll
            for (int ri = 0; ri < 8; ri++) dr[ri] = buf[s][ty + 16 * ri];
#pragma unroll
            for (int ci = 0; ci < 8; ci++) dc[ci] = buf[s][tx + 16 * ci];
#pragma unroll
            for (int ri = 0; ri < 8; ri++)
#pragma unroll
                for (int ci = 0; ci < 8; ci++)
                    acc[ri][ci] += dr[ri] * dc[ci];
            if (tid < HIDDEN) xsum += buf[s][tid];
        }
    }

    // ---- write per-class stats ----
    float* S = g_S + c * HIDDEN * HIDDEN;
#pragma unroll
    for (int ri = 0; ri < 8; ri++) {
        const int r = ty + 16 * ri;
#pragma unroll
        for (int ci = 0; ci < 8; ci++)
            S[r * HIDDEN + tx + 16 * ci] = acc[ri][ci];
    }
    if (tid < HIDDEN) g_sum[c * HIDDEN + tid] = xsum;
    if (tid == 0)     g_n[c] = n;
}

// ---------------- Stage B: elementwise reconstruction, centers fused ----------------
// out[c,j] = class_cov[c,j] + S_c - mu_j s_c^T - s_c mu_j^T + n_c mu_j mu_j^T
// grid (N_CLASS, 16): z selects an 8-row slab; each CTA handles ALL 4 centers,
// so each S element is read ONCE. 256 threads = 8 rows x 32 float4.
// All 5 loads (1 S + 4 cov) batched before compute.
__global__ void __launch_bounds__(256, 5) stageB_kernel(
    const float* __restrict__ class_mu,   // only class_mu[0] used: [N_CENTER][HIDDEN]
    const float* __restrict__ class_cov,
    float* __restrict__ out)
{
    const int c = blockIdx.x;
    const int z = blockIdx.y;

    __shared__ float s_mu[N_CENTER][HIDDEN];
    __shared__ float s_s[HIDDEN];
    __shared__ float s_n;

    const int tid = threadIdx.x;
    // load 4 mu vectors (512 floats) + s (128) + n
    {
        const int i0 = tid;           // 0..255
        s_mu[i0 >> 7][i0 & 127]             = class_mu[i0];
        s_mu[(i0 + 256) >> 7][i0 & 127]     = class_mu[i0 + 256];
    }
    if (tid < HIDDEN) s_s[tid] = g_sum[c * HIDDEN + tid];
    if (tid == 0)     s_n = (float)g_n[c];

    const int r    = z * 8 + (tid >> 5);   // global row (warp-uniform)
    const int cf4  = tid & 31;             // float4 column index

    const float4* S4 = (const float4*)(g_S + (size_t)c * HIDDEN * HIDDEN);
    const int qS = r * 32 + cf4;

    // ---- batch all global loads ----
    float4 Sv = S4[qS];
    float4 cv[N_CENTER];
#pragma unroll
    for (int j = 0; j < N_CENTER; j++) {
        const float4* cov4 = (const float4*)(class_cov
            + ((size_t)(c * N_CENTER + j)) * HIDDEN * HIDDEN);
        cv[j] = cov4[qS];
    }

    __syncthreads();
    const float nf = s_n;
    const float  sr = s_s[r];                        // warp-uniform scalar
    const float4 sc = ((const float4*)s_s)[cf4];     // column chunk of s

#pragma unroll
    for (int j = 0; j < N_CENTER; j++) {
        const float mr = s_mu[j][r];                 // warp-uniform
        const float tr = fmaf(nf, mr, -sr);          // n*mu_r - s_r
        const float4 mc = ((const float4*)s_mu[j])[cf4];
        float4 o;
        o.x = cv[j].x + Sv.x - mr * sc.x + tr * mc.x;
        o.y = cv[j].y + Sv.y - mr * sc.y + tr * mc.y;
        o.z = cv[j].z + Sv.z - mr * sc.z + tr * mc.z;
        o.w = cv[j].w + Sv.w - mr * sc.w + tr * mc.w;
        float4* out4 = (float4*)(out
            + ((size_t)(c * N_CENTER + j)) * HIDDEN * HIDDEN);
        out4[qS] = o;
    }
}

extern "C" void kernel_launch(void* const* d_in, const int* in_sizes, int n_in,
                              void* d_out, int out_size) {
    const float* x         = (const float*)d_in[0];
    const int*   y         = (const int*)d_in[1];
    const float* class_mu  = (const float*)d_in[2];
    const float* class_cov = (const float*)d_in[3];
    float*       out       = (float*)d_out;

    stageA_kernel<<<N_CLASS, 256>>>(x, y);
    dim3 gridB(N_CLASS, 16);
    stageB_kernel<<<gridB, 256>>>(class_mu, class_cov, out);
}

// round 15
// speedup vs baseline: 1.2361x; 1.0052x over previous
#include <cuda_runtime.h>

#define N_CLASS  100
#define N_CENTER 4
#define HIDDEN   128
#define BATCH    2048
#define CHUNK    8

// Fully fused, centers-fused, row-split: one CTA per (class c, row-half h).
//  1) compact class-c sample list (deterministic warp-scan order),
//  2) accumulate S_c rows [h*64, h*64+64) x 128 in acc[4][8] registers,
//     and s_c = sum x (full 128) in smem,
//  3) epilogue for ALL 4 centers of this row slab, straight from registers:
//     out[c,j] = class_cov[c,j] + S - mu_r*s_cc + (n*mu_r - s_r)*mu_cc.
// S never touches global memory; single launch.
__global__ void __launch_bounds__(256, 3) cov_fused2_kernel(
    const float* __restrict__ x,          // [BATCH, HIDDEN]
    const int*   __restrict__ y,          // [BATCH]
    const float* __restrict__ class_mu,   // only class_mu[0]: [N_CENTER][HIDDEN]
    const float* __restrict__ class_cov,  // [N_CLASS, N_CENTER, HIDDEN, HIDDEN]
    float* __restrict__ out)
{
    const int c = blockIdx.x;   // class
    const int h = blockIdx.y;   // row half (0/1): rows [h*64, h*64+64)

    __shared__ float s_d[2][CHUNK][HIDDEN];
    __shared__ int   s_list[BATCH];
    __shared__ int   s_wsum[8];
    __shared__ float s_mu[N_CENTER][HIDDEN];
    __shared__ float s_s[HIDDEN];

    const int tid  = threadIdx.x;
    const int lane = tid & 31;
    const int w    = tid >> 5;
    const int tx   = tid & 15;    // col group: cols tx + 16*ci, ci<8
    const int ty   = tid >> 4;    // row group: rows h*64 + ty + 16*ri, ri<4

    // all 4 mu vectors (512 floats over 256 threads)
    s_mu[tid >> 7][tid & 127]           = class_mu[tid];
    s_mu[(tid + 256) >> 7][tid & 127]   = class_mu[tid + 256];

    // ---- Phase 1: deterministic in-CTA compaction ----
    int loc[8];
    int cnt = 0;
    {
        const int4* y4 = (const int4*)y;
        int4 a = y4[tid * 2];
        int4 b = y4[tid * 2 + 1];
        const int base = tid * 8;
        if (a.x == c) loc[cnt++] = base + 0;
        if (a.y == c) loc[cnt++] = base + 1;
        if (a.z == c) loc[cnt++] = base + 2;
        if (a.w == c) loc[cnt++] = base + 3;
        if (b.x == c) loc[cnt++] = base + 4;
        if (b.y == c) loc[cnt++] = base + 5;
        if (b.z == c) loc[cnt++] = base + 6;
        if (b.w == c) loc[cnt++] = base + 7;
    }
    int inc = cnt;
#pragma unroll
    for (int d = 1; d < 32; d <<= 1) {
        int v = __shfl_up_sync(0xffffffffu, inc, d);
        if (lane >= d) inc += v;
    }
    if (lane == 31) s_wsum[w] = inc;
    __syncthreads();
    int woff = 0, n = 0;
#pragma unroll
    for (int k = 0; k < 8; k++) {
        int s = s_wsum[k];
        if (k < w) woff += s;
        n += s;
    }
    const int off = woff + inc - cnt;
#pragma unroll
    for (int i = 0; i < 8; i++)
        if (i < cnt) s_list[off + i] = loc[i];
    __syncthreads();

    // ---- Phase 2: S rows (this half) in registers, s_c in smem ----
    float acc[4][8];
#pragma unroll
    for (int ri = 0; ri < 4; ri++)
#pragma unroll
        for (int ci = 0; ci < 8; ci++) acc[ri][ci] = 0.0f;
    float xsum = 0.0f;   // threads < 128 accumulate s_c[tid] (full vector)

    const float4* x4 = (const float4*)x;
    const int nchunks = (n + CHUNK - 1) / CHUNK;
    const int gs = tid >> 5;   // sample row within chunk
    const int gq = tid & 31;   // float4 within row
    const int rbase = h * 64;

    if (nchunks > 0) {
        float4 v = make_float4(0.f, 0.f, 0.f, 0.f);
        if (gs < n) v = x4[s_list[gs] * 32 + gq];
        ((float4*)s_d[0][gs])[gq] = v;
    }

    for (int k = 0; k < nchunks; k++) {
        __syncthreads();
        if (k + 1 < nchunks) {
            const int s0 = (k + 1) * CHUNK;
            float4 v = make_float4(0.f, 0.f, 0.f, 0.f);
            if (s0 + gs < n) v = x4[s_list[s0 + gs] * 32 + gq];
            ((float4*)s_d[(k + 1) & 1][gs])[gq] = v;
        }
        const float (*buf)[HIDDEN] = s_d[k & 1];
#pragma unroll
        for (int s = 0; s < CHUNK; s++) {
            float dr[4], dc[8];
#pragma unroll
            for (int ri = 0; ri < 4; ri++) dr[ri] = buf[s][rbase + ty + 16 * ri];
#pragma unroll
            for (int ci = 0; ci < 8; ci++) dc[ci] = buf[s][tx + 16 * ci];
#pragma unroll
            for (int ri = 0; ri < 4; ri++)
#pragma unroll
                for (int ci = 0; ci < 8; ci++)
                    acc[ri][ci] += dr[ri] * dc[ci];
            if (tid < HIDDEN) xsum += buf[s][tid];
        }
    }
    if (tid < HIDDEN) s_s[tid] = xsum;
    __syncthreads();

    // ---- Phase 3: epilogue for all 4 centers of this row slab ----
    const float nf = (float)n;
    float sc[8];
#pragma unroll
    for (int ci = 0; ci < 8; ci++) sc[ci] = s_s[tx + 16 * ci];

#pragma unroll
    for (int j = 0; j < N_CENTER; j++) {
        const size_t jb = ((size_t)(c * N_CENTER + j)) * HIDDEN * HIDDEN;
        float mc[8];
#pragma unroll
        for (int ci = 0; ci < 8; ci++) mc[ci] = s_mu[j][tx + 16 * ci];
#pragma unroll
        for (int ri = 0; ri < 4; ri++) {
            const int r = rbase + ty + 16 * ri;
            const float mr = s_mu[j][r];
            const float tr = fmaf(nf, mr, -s_s[r]);   // n*mu_r - s_r
            const float* cvrow = class_cov + jb + (size_t)r * HIDDEN;
            float*       orow  = out       + jb + (size_t)r * HIDDEN;
            float cv[8];
#pragma unroll
            for (int ci = 0; ci < 8; ci++) cv[ci] = cvrow[tx + 16 * ci];  // batched
#pragma unroll
            for (int ci = 0; ci < 8; ci++) {
                float o = acc[ri][ci] + cv[ci];
                o = fmaf(-mr, sc[ci], o);
                o = fmaf(tr, mc[ci], o);
                orow[tx + 16 * ci] = o;
            }
        }
    }
}

extern "C" void kernel_launch(void* const* d_in, const int* in_sizes, int n_in,
                              void* d_out, int out_size) {
    const float* x         = (const float*)d_in[0];
    const int*   y         = (const int*)d_in[1];
    const float* class_mu  = (const float*)d_in[2];
    const float* class_cov = (const float*)d_in[3];
    float*       out       = (float*)d_out;

    dim3 grid(N_CLASS, 2);
    cov_fused2_kernel<<<grid, 256>>>(x, y, class_mu, class_cov, out);
}

// round 16
// speedup vs baseline: 1.4297x; 1.1566x over previous
#include <cuda_runtime.h>

#define N_CLASS  100
#define N_CENTER 4
#define HIDDEN   128
#define BATCH    2048
#define CHUNK    8
#define SLAB     32           // rows per CTA
#define SPAD     132          // padded row stride (floats) for s_S

// Fused, centers-fused, quarter-row-split: one CTA per (class c, slab z).
//  1) compact class-c sample list (deterministic warp-scan order),
//  2) accumulate S rows [z*32, z*32+32) x 128 in acc[2][8] regs; s_c in smem,
//  3) dump S-slab to smem, then float4 epilogue for ALL 4 centers:
//     out[c,j] = class_cov[c,j] + S - mu_r*s_cc + (n*mu_r - s_r)*mu_cc.
// Single launch; S never touches global memory; 400 CTAs = 1 wave @ 3/SM.
__global__ void __launch_bounds__(256, 3) cov_fused3_kernel(
    const float* __restrict__ x,          // [BATCH, HIDDEN]
    const int*   __restrict__ y,          // [BATCH]
    const float* __restrict__ class_mu,   // only class_mu[0]: [N_CENTER][HIDDEN]
    const float* __restrict__ class_cov,  // [N_CLASS, N_CENTER, HIDDEN, HIDDEN]
    float* __restrict__ out)
{
    const int c = blockIdx.x;        // class
    const int z = blockIdx.y;        // row slab: rows [z*32, z*32+32)

    __shared__ float s_d[2][CHUNK][HIDDEN];
    __shared__ int   s_list[BATCH];
    __shared__ int   s_wsum[8];
    __shared__ float s_mu[N_CENTER][HIDDEN];
    __shared__ float s_s[HIDDEN];
    __shared__ float s_S[SLAB][SPAD];     // S slab, padded vs bank conflicts

    const int tid  = threadIdx.x;
    const int lane = tid & 31;
    const int w    = tid >> 5;
    const int tx   = tid & 15;       // col group: cols tx + 16*ci, ci<8
    const int ty   = tid >> 4;       // row group: rows rbase + ty + 16*ri, ri<2

    // all 4 mu vectors (512 floats over 256 threads)
    s_mu[tid >> 7][tid & 127]         = class_mu[tid];
    s_mu[(tid + 256) >> 7][tid & 127] = class_mu[tid + 256];

    // ---- Phase 1: deterministic in-CTA compaction ----
    int loc[8];
    int cnt = 0;
    {
        const int4* y4 = (const int4*)y;
        int4 a = y4[tid * 2];
        int4 b = y4[tid * 2 + 1];
        const int base = tid * 8;
        if (a.x == c) loc[cnt++] = base + 0;
        if (a.y == c) loc[cnt++] = base + 1;
        if (a.z == c) loc[cnt++] = base + 2;
        if (a.w == c) loc[cnt++] = base + 3;
        if (b.x == c) loc[cnt++] = base + 4;
        if (b.y == c) loc[cnt++] = base + 5;
        if (b.z == c) loc[cnt++] = base + 6;
        if (b.w == c) loc[cnt++] = base + 7;
    }
    int inc = cnt;
#pragma unroll
    for (int d = 1; d < 32; d <<= 1) {
        int v = __shfl_up_sync(0xffffffffu, inc, d);
        if (lane >= d) inc += v;
    }
    if (lane == 31) s_wsum[w] = inc;
    __syncthreads();
    int woff = 0, n = 0;
#pragma unroll
    for (int k = 0; k < 8; k++) {
        int s = s_wsum[k];
        if (k < w) woff += s;
        n += s;
    }
    const int off = woff + inc - cnt;
#pragma unroll
    for (int i = 0; i < 8; i++)
        if (i < cnt) s_list[off + i] = loc[i];
    __syncthreads();

    // ---- Phase 2: S slab in registers, s_c in smem ----
    float acc[2][8];
#pragma unroll
    for (int ri = 0; ri < 2; ri++)
#pragma unroll
        for (int ci = 0; ci < 8; ci++) acc[ri][ci] = 0.0f;
    float xsum = 0.0f;

    const float4* x4 = (const float4*)x;
    const int nchunks = (n + CHUNK - 1) / CHUNK;
    const int gs = tid >> 5;
    const int gq = tid & 31;
    const int rbase = z * SLAB;

    if (nchunks > 0) {
        float4 v = make_float4(0.f, 0.f, 0.f, 0.f);
        if (gs < n) v = x4[s_list[gs] * 32 + gq];
        ((float4*)s_d[0][gs])[gq] = v;
    }

    for (int k = 0; k < nchunks; k++) {
        __syncthreads();
        if (k + 1 < nchunks) {
            const int s0 = (k + 1) * CHUNK;
            float4 v = make_float4(0.f, 0.f, 0.f, 0.f);
            if (s0 + gs < n) v = x4[s_list[s0 + gs] * 32 + gq];
            ((float4*)s_d[(k + 1) & 1][gs])[gq] = v;
        }
        const float (*buf)[HIDDEN] = s_d[k & 1];
#pragma unroll
        for (int s = 0; s < CHUNK; s++) {
            float dr[2], dc[8];
#pragma unroll
            for (int ri = 0; ri < 2; ri++) dr[ri] = buf[s][rbase + ty + 16 * ri];
#pragma unroll
            for (int ci = 0; ci < 8; ci++) dc[ci] = buf[s][tx + 16 * ci];
#pragma unroll
            for (int ri = 0; ri < 2; ri++)
#pragma unroll
                for (int ci = 0; ci < 8; ci++)
                    acc[ri][ci] += dr[ri] * dc[ci];
            if (tid < HIDDEN) xsum += buf[s][tid];
        }
    }
    if (tid < HIDDEN) s_s[tid] = xsum;

    // dump S slab to smem
#pragma unroll
    for (int ri = 0; ri < 2; ri++)
#pragma unroll
        for (int ci = 0; ci < 8; ci++)
            s_S[ty + 16 * ri][tx + 16 * ci] = acc[ri][ci];
    __syncthreads();

    // ---- Phase 3: float4 epilogue for all 4 centers ----
    // thread -> row r_l = tid>>3 (0..31), f4 cols (tid&7) + 8*i, i<4.
    const float nf = (float)n;
    const int r_l = tid >> 3;
    const int r   = rbase + r_l;
    const int q0  = tid & 7;
    const float sr = s_s[r];

    float4 Sv[4], sc4[4];
#pragma unroll
    for (int i = 0; i < 4; i++) {
        Sv[i]  = ((const float4*)&s_S[r_l][0])[q0 + 8 * i];
        sc4[i] = ((const float4*)s_s)[q0 + 8 * i];
    }

#pragma unroll
    for (int j = 0; j < N_CENTER; j++) {
        const size_t jb = ((size_t)(c * N_CENTER + j)) * HIDDEN * HIDDEN;
        const float4* cov4 = (const float4*)(class_cov + jb);
        float4*       out4 = (float4*)(out + jb);
        const float mr = s_mu[j][r];
        const float tr = fmaf(nf, mr, -sr);       // n*mu_r - s_r
        float4 cv[4], mc[4];
#pragma unroll
        for (int i = 0; i < 4; i++) cv[i] = cov4[r * 32 + q0 + 8 * i];   // batched
#pragma unroll
        for (int i = 0; i < 4; i++) mc[i] = ((const float4*)s_mu[j])[q0 + 8 * i];
#pragma unroll
        for (int i = 0; i < 4; i++) {
            float4 o;
            o.x = cv[i].x + Sv[i].x - mr * sc4[i].x + tr * mc[i].x;
            o.y = cv[i].y + Sv[i].y - mr * sc4[i].y + tr * mc[i].y;
            o.z = cv[i].z + Sv[i].z - mr * sc4[i].z + tr * mc[i].z;
            o.w = cv[i].w + Sv[i].w - mr * sc4[i].w + tr * mc[i].w;
            out4[r * 32 + q0 + 8 * i] = o;
        }
    }
}

extern "C" void kernel_launch(void* const* d_in, const int* in_sizes, int n_in,
                              void* d_out, int out_size) {
    const float* x         = (const float*)d_in[0];
    const int*   y         = (const int*)d_in[1];
    const float* class_mu  = (const float*)d_in[2];
    const float* class_cov = (const float*)d_in[3];
    float*       out       = (float*)d_out;

    dim3 grid(N_CLASS, HIDDEN / SLAB);
    cov_fused3_kernel<<<grid, 256>>>(x, y, class_mu, class_cov, out);
}